// round 5
// baseline (speedup 1.0000x reference)
#include <cuda_runtime.h>
#include <math.h>

#define G        512
#define S        32
#define PTS      8
#define SEGS_PER (PTS - 1)           // 7
#define NSEG     (S * SEGS_PER)      // 224
#define TILE     16
#define NTHREADS 128                 // 16 x 8, each thread does 2 pixels
#define TPR      (G / TILE)          // 32 tiles per row
#define NTILES   (TPR * TPR)         // 1024
#define NBLOCKS  592                 // 148 SMs * 4 CTAs

__device__ int g_ctr;                // dynamic tile queue counter (reset per launch)

// ---------------------------------------------------------------------------
// Persistent-CTA renderer: 592 CTAs, dynamic tile queue over 1024 16x16 tiles.
// Per CTA (once):  stage clamped pixel-space points + per-stroke {2t, 1/4t^2}.
// Per tile:        cull 224 segments vs tile center (capsule test), compact
//                  survivors to SMEM; 2 pixels/thread min of scaled squared
//                  distance; one sqrt at the end (min is monotone under sqrt).
// Next-tile atomicAdd issues before the cull barrier to hide its latency.
// ---------------------------------------------------------------------------
__global__ void __launch_bounds__(NTHREADS)
render_kernel(const float* __restrict__ strokes,
              const float* __restrict__ thick,
              float* __restrict__ out) {
    __shared__ float  s_pts[S * PTS * 2];   // clamped * 512 coords
    __shared__ float2 s_t[S];               // {r = 2t, sc = 1/(4t^2)}
    __shared__ float4 s_a[NSEG];            // vx, vy, ex, ey
    __shared__ float2 s_b[NSEG];            // invd2, scale
    __shared__ int    s_n;
    __shared__ int    s_next;

    const int tid = threadIdx.x;

    // ---- Stage inputs once per CTA (512 floats = 128 * float4) ----
    {
        float4 v = ((const float4*)strokes)[tid];
        float4 c;
        c.x = __saturatef(v.x) * (float)G;
        c.y = __saturatef(v.y) * (float)G;
        c.z = __saturatef(v.z) * (float)G;
        c.w = __saturatef(v.w) * (float)G;
        ((float4*)s_pts)[tid] = c;
        if (tid < S) {
            float t = fmaxf(fmaf(thick[tid], 2.0f, 0.5f), 0.5f);
            float r = 2.0f * t;
            s_t[tid] = make_float2(r, __fdividef(1.0f, r * r));
        }
    }
    if (tid == 0) s_n = 0;
    __syncthreads();

    const float RMAX = (TILE - 1) * 0.5f * 1.41421356f + 1.0f;
    const int tx = tid & (TILE - 1);
    const int ty = tid >> 4;

    int tile = blockIdx.x;

    while (tile < NTILES) {
        const int ti = (tile >> 5) * TILE;       // row base
        const int tj = (tile & (TPR - 1)) * TILE; // col base (contiguous)

        const float cx = (float)ti + (TILE - 1) * 0.5f;
        const float cy = (float)tj + (TILE - 1) * 0.5f;

        // Grab the next tile early; latency overlaps the cull phase.
        if (tid == 0) s_next = atomicAdd(&g_ctr, 1) + NBLOCKS;

        // ---- Cull 224 segments (each thread handles up to 2) ----
        #pragma unroll
        for (int seg = tid; seg < NSEG; seg += NTHREADS) {
            const int s = seg / SEGS_PER;
            const int base = (seg + s) * 2;      // (s*PTS + k)*2, k = seg - 7s
            float2 vv = *(const float2*)(s_pts + base);
            float2 ww = *(const float2*)(s_pts + base + 2);

            float ex = ww.x - vv.x;
            float ey = ww.y - vv.y;
            float d2 = ex * ex + ey * ey;
            float invd2 = __fdividef(1.0f, d2 + 1e-5f);
            float2 rs = s_t[s];

            float dx  = cx - vv.x;
            float dy  = cy - vv.y;
            float dot = dx * ex + dy * ey;
            float fr  = __saturatef(dot * invd2);
            float ddx = fmaf(-fr, ex, dx);
            float ddy = fmaf(-fr, ey, dy);
            float dq  = ddx * ddx + ddy * ddy;
            float thr = rs.x + RMAX;
            if (dq <= thr * thr) {
                int p = atomicAdd(&s_n, 1);
                s_a[p] = make_float4(vv.x, vv.y, ex, ey);
                s_b[p] = make_float2(invd2, rs.y);
            }
        }
        __syncthreads();

        // ---- Render: 2 pixels per thread (rows ty and ty+8) ----
        const int n  = s_n;
        const int nx = s_next;
        const float px0 = (float)(ti + ty);
        const float py  = (float)(tj + tx);

        float m0 = 1e30f;
        float m1 = 1e30f;
        #pragma unroll 2
        for (int q = 0; q < n; q++) {
            float4 a = s_a[q];
            float2 b = s_b[q];
            float dx0  = px0 - a.x;
            float dx1  = dx0 + 8.0f;
            float dy   = py - a.y;
            float dyey = dy * a.w;
            float dot0 = fmaf(dx0, a.z, dyey);
            float dot1 = fmaf(8.0f, a.z, dot0);
            float fr0  = __saturatef(dot0 * b.x);
            float fr1  = __saturatef(dot1 * b.x);
            float ddx0 = fmaf(-fr0, a.z, dx0);
            float ddy0 = fmaf(-fr0, a.w, dy);
            float ddx1 = fmaf(-fr1, a.z, dx1);
            float ddy1 = fmaf(-fr1, a.w, dy);
            float dq0  = fmaf(ddx0, ddx0, ddy0 * ddy0);
            float dq1  = fmaf(ddx1, ddx1, ddy1 * ddy1);
            m0 = fminf(m0, dq0 * b.y);
            m1 = fminf(m1, dq1 * b.y);
        }

        float* o = out + (ti + ty) * G + (tj + tx);
        o[0]     = fminf(sqrtf(m0), 1.0f);
        o[8 * G] = fminf(sqrtf(m1), 1.0f);

        if (tid == 0) s_n = 0;
        __syncthreads();          // protects s_a/s_b reuse and s_n reset
        tile = nx;
    }
}

extern "C" void kernel_launch(void* const* d_in, const int* in_sizes, int n_in,
                              void* d_out, int out_size) {
    // metadata order: strokes [32,8,2] f32 (512 elems), thicknesses [32] f32.
    const float* strokes = (const float*)d_in[0];
    const float* thick   = (const float*)d_in[1];
    if (n_in >= 2 && in_sizes[0] == S && in_sizes[1] == S * PTS * 2) {
        strokes = (const float*)d_in[1];
        thick   = (const float*)d_in[0];
    }
    float* out = (float*)d_out;

    // Reset the dynamic tile counter (graph-capturable, no allocation).
    void* ctr_ptr = nullptr;
    cudaGetSymbolAddress(&ctr_ptr, g_ctr);
    cudaMemsetAsync(ctr_ptr, 0, sizeof(int));

    render_kernel<<<NBLOCKS, NTHREADS>>>(strokes, thick, out);
}

// round 6
// speedup vs baseline: 1.1402x; 1.1402x over previous
#include <cuda_runtime.h>
#include <math.h>

#define G        512
#define S        32
#define PTS      8
#define SEGS_PER (PTS - 1)           // 7
#define NSEG     (S * SEGS_PER)      // 224
#define TILE     32                  // 32x32 pixel tiles
#define NTHREADS 512                 // 32 x 16, each thread does 2 pixels
#define TPR      (G / TILE)          // 16 tiles per row -> 256 CTAs

// ---------------------------------------------------------------------------
// One 32x32 tile per 512-thread CTA (256 CTAs total, single wave).
// Threads 0..223 each own one segment: load its 2 points + thickness from
// global (issued before the first barrier so latency hides under it),
// capsule-cull vs tile center, compact survivors to SMEM.
// Then all 512 threads render 2 pixels each (rows ty, ty+16) over survivors,
// tracking min scaled-squared distance; one sqrt at the end.
// ---------------------------------------------------------------------------
__global__ void __launch_bounds__(NTHREADS)
render_kernel(const float* __restrict__ strokes,
              const float* __restrict__ thick,
              float* __restrict__ out) {
    __shared__ float4 s_a[NSEG];     // vx, vy, ex, ey
    __shared__ float2 s_b[NSEG];     // invd2, scale
    __shared__ int    s_n;

    const int tid = threadIdx.x;

    // ---- Issue segment loads early (latency overlaps the barrier) ----
    float2 p0 = make_float2(0.f, 0.f), p1 = p0;
    float  tk = 0.f;
    int s = 0;
    if (tid < NSEG) {
        s = (tid * 9363) >> 16;              // tid / 7 for tid < 224
        const int k = tid - s * SEGS_PER;
        const float2* pts = (const float2*)(strokes) + s * PTS + k;
        p0 = pts[0];
        p1 = pts[1];
        tk = thick[s];
    }
    if (tid == 0) s_n = 0;
    __syncthreads();

    const int ti = blockIdx.y * TILE;        // row base (out stride G)
    const int tj = blockIdx.x * TILE;        // col base (contiguous)

    const float cx   = (float)ti + (TILE - 1) * 0.5f;
    const float cy   = (float)tj + (TILE - 1) * 0.5f;
    const float RMAX = (TILE - 1) * 0.5f * 1.41421356f + 1.0f;

    // ---- Cull: one segment per thread ----
    if (tid < NSEG) {
        float vx = __saturatef(p0.x) * (float)G;
        float vy = __saturatef(p0.y) * (float)G;
        float wx = __saturatef(p1.x) * (float)G;
        float wy = __saturatef(p1.y) * (float)G;

        float ex = wx - vx;
        float ey = wy - vy;
        float d2 = ex * ex + ey * ey;
        float invd2 = __fdividef(1.0f, d2 + 1e-5f);

        float t = fmaxf(fmaf(tk, 2.0f, 0.5f), 0.5f);
        float r = 2.0f * t;

        float dx  = cx - vx;
        float dy  = cy - vy;
        float dot = dx * ex + dy * ey;
        float fr  = __saturatef(dot * invd2);
        float ddx = fmaf(-fr, ex, dx);
        float ddy = fmaf(-fr, ey, dy);
        float dq  = ddx * ddx + ddy * ddy;
        float thr = r + RMAX;
        if (dq <= thr * thr) {
            int p = atomicAdd(&s_n, 1);
            s_a[p] = make_float4(vx, vy, ex, ey);
            s_b[p] = make_float2(invd2, __fdividef(1.0f, r * r));
        }
    }
    __syncthreads();

    // ---- Render: 2 pixels per thread (rows ty and ty+16) ----
    const int tx = tid & (TILE - 1);
    const int ty = tid >> 5;                 // 0..15
    const float px0 = (float)(ti + ty);
    const float py  = (float)(tj + tx);
    const int n = s_n;

    float m0 = 1e30f;
    float m1 = 1e30f;
    #pragma unroll 2
    for (int q = 0; q < n; q++) {
        float4 a = s_a[q];
        float2 b = s_b[q];
        float dx0  = px0 - a.x;
        float dx1  = dx0 + 16.0f;
        float dy   = py - a.y;
        float dyey = dy * a.w;
        float dot0 = fmaf(dx0, a.z, dyey);
        float dot1 = fmaf(16.0f, a.z, dot0);
        float fr0  = __saturatef(dot0 * b.x);
        float fr1  = __saturatef(dot1 * b.x);
        float ddx0 = fmaf(-fr0, a.z, dx0);
        float ddy0 = fmaf(-fr0, a.w, dy);
        float ddx1 = fmaf(-fr1, a.z, dx1);
        float ddy1 = fmaf(-fr1, a.w, dy);
        float dq0  = fmaf(ddx0, ddx0, ddy0 * ddy0);
        float dq1  = fmaf(ddx1, ddx1, ddy1 * ddy1);
        m0 = fminf(m0, dq0 * b.y);
        m1 = fminf(m1, dq1 * b.y);
    }

    float* o = out + (ti + ty) * G + (tj + tx);
    o[0]      = fminf(sqrtf(m0), 1.0f);
    o[16 * G] = fminf(sqrtf(m1), 1.0f);
}

extern "C" void kernel_launch(void* const* d_in, const int* in_sizes, int n_in,
                              void* d_out, int out_size) {
    // metadata order: strokes [32,8,2] f32 (512 elems), thicknesses [32] f32.
    const float* strokes = (const float*)d_in[0];
    const float* thick   = (const float*)d_in[1];
    if (n_in >= 2 && in_sizes[0] == S && in_sizes[1] == S * PTS * 2) {
        strokes = (const float*)d_in[1];
        thick   = (const float*)d_in[0];
    }
    float* out = (float*)d_out;

    dim3 block(NTHREADS);
    dim3 grid(TPR, TPR);
    render_kernel<<<grid, block>>>(strokes, thick, out);
}

// round 7
// speedup vs baseline: 1.4928x; 1.3092x over previous
#include <cuda_runtime.h>
#include <math.h>

#define G        512
#define S        32
#define PTS      8
#define SEGS_PER (PTS - 1)           // 7
#define NSEG     (S * SEGS_PER)      // 224
#define TILE     16
#define NTHREADS 128                 // 8 thread-cols x 16 rows, 2 px/thread
#define TPR      (G / TILE)          // 32 tiles per row

// ---------------------------------------------------------------------------
// One 16x16 tile per 128-thread CTA (1024 CTAs, single wave, ~28 warps/SM).
// Cull: 224 segments in 2 warp-uniform rounds (128 + 96). Each thread loads
//   its segment's points + thickness straight from global (issued before the
//   first barrier), capsule-culls vs tile center, then warp-ballot compacts
//   survivors: one atomicAdd per warp per round instead of per lane.
// Render: each thread owns two horizontally adjacent pixels; min of scaled
//   squared distance over survivors; single sqrt; one float2 store.
// ---------------------------------------------------------------------------
__global__ void __launch_bounds__(NTHREADS)
render_kernel(const float* __restrict__ strokes,
              const float* __restrict__ thick,
              float* __restrict__ out) {
    __shared__ float4 s_a[NSEG];     // vx, vy, ex, ey
    __shared__ float2 s_b[NSEG];     // invd2, scale
    __shared__ int    s_n;

    const int tid  = threadIdx.x;
    const int lane = tid & 31;
    const int wid  = tid >> 5;

    // ---- Issue segment loads early (latency hides under the first barrier) ----
    // Round 1: seg = tid (0..127). Round 2: seg = 128 + tid (warps 0..2 only).
    int   s0 = (tid * 9363) >> 16;                 // tid / 7
    int   i0 = s0 * PTS + (tid - s0 * SEGS_PER);   // point index
    float2 a0 = ((const float2*)strokes)[i0];
    float2 b0 = ((const float2*)strokes)[i0 + 1];
    float  t0 = thick[s0];

    int    seg1 = 128 + tid;
    float2 a1 = make_float2(0.f, 0.f), b1 = a1;
    float  t1 = 0.f;
    if (wid < 3) {                                 // seg1 in [128, 224)
        int s1 = (seg1 * 9363) >> 16;
        int i1 = s1 * PTS + (seg1 - s1 * SEGS_PER);
        a1 = ((const float2*)strokes)[i1];
        b1 = ((const float2*)strokes)[i1 + 1];
        t1 = thick[s1];
    }

    if (tid == 0) s_n = 0;
    __syncthreads();

    const int ti = blockIdx.y * TILE;              // row base (out stride G)
    const int tj = blockIdx.x * TILE;              // col base (contiguous)

    const float cx   = (float)ti + (TILE - 1) * 0.5f;
    const float cy   = (float)tj + (TILE - 1) * 0.5f;
    const float RMAX = (TILE - 1) * 0.5f * 1.41421356f + 1.0f;

    // ---- Cull round helper (inlined twice) ----
    #define CULL_ROUND(P0, P1, TK)                                            \
    {                                                                         \
        float vx = __saturatef((P0).x) * (float)G;                            \
        float vy = __saturatef((P0).y) * (float)G;                            \
        float wx = __saturatef((P1).x) * (float)G;                            \
        float wy = __saturatef((P1).y) * (float)G;                            \
        float ex = wx - vx;                                                   \
        float ey = wy - vy;                                                   \
        float d2 = ex * ex + ey * ey;                                         \
        float invd2 = __fdividef(1.0f, d2 + 1e-5f);                           \
        float t  = fmaxf(fmaf((TK), 2.0f, 0.5f), 0.5f);                       \
        float r  = 2.0f * t;                                                  \
        float dx  = cx - vx;                                                  \
        float dy  = cy - vy;                                                  \
        float dot = dx * ex + dy * ey;                                        \
        float fr  = __saturatef(dot * invd2);                                 \
        float ddx = fmaf(-fr, ex, dx);                                        \
        float ddy = fmaf(-fr, ey, dy);                                        \
        float dq  = ddx * ddx + ddy * ddy;                                    \
        float thr = r + RMAX;                                                 \
        bool keep = (dq <= thr * thr);                                        \
        unsigned bal = __ballot_sync(0xffffffffu, keep);                      \
        int base = 0;                                                         \
        if (lane == 0 && bal) base = atomicAdd(&s_n, __popc(bal));            \
        base = __shfl_sync(0xffffffffu, base, 0);                             \
        if (keep) {                                                           \
            int p = base + __popc(bal & ((1u << lane) - 1u));                 \
            s_a[p] = make_float4(vx, vy, ex, ey);                             \
            s_b[p] = make_float2(invd2, __fdividef(1.0f, r * r));             \
        }                                                                     \
    }

    CULL_ROUND(a0, b0, t0);
    if (wid < 3) CULL_ROUND(a1, b1, t1);
    #undef CULL_ROUND

    __syncthreads();

    // ---- Render: 2 horizontally adjacent pixels per thread ----
    const int tx = tid & 7;                        // thread-col: px cols 2tx, 2tx+1
    const int ty = tid >> 3;                       // row 0..15
    const float px  = (float)(ti + ty);            // row coord (meshgrid 'ij' x)
    const float py0 = (float)(tj + 2 * tx);        // col coord
    const int n = s_n;

    float m0 = 1e30f;
    float m1 = 1e30f;
    #pragma unroll 2
    for (int q = 0; q < n; q++) {
        float4 a = s_a[q];
        float2 b = s_b[q];
        float dx   = px - a.x;
        float dy0  = py0 - a.y;
        float dy1  = dy0 + 1.0f;
        float dxez = dx * a.z;
        float dot0 = fmaf(dy0, a.w, dxez);
        float dot1 = dot0 + a.w;
        float fr0  = __saturatef(dot0 * b.x);
        float fr1  = __saturatef(dot1 * b.x);
        float ddx0 = fmaf(-fr0, a.z, dx);
        float ddy0 = fmaf(-fr0, a.w, dy0);
        float ddx1 = fmaf(-fr1, a.z, dx);
        float ddy1 = fmaf(-fr1, a.w, dy1);
        float dq0  = fmaf(ddx0, ddx0, ddy0 * ddy0);
        float dq1  = fmaf(ddx1, ddx1, ddy1 * ddy1);
        m0 = fminf(m0, dq0 * b.y);
        m1 = fminf(m1, dq1 * b.y);
    }

    float2 res = make_float2(fminf(sqrtf(m0), 1.0f), fminf(sqrtf(m1), 1.0f));
    *(float2*)(out + (ti + ty) * G + (tj + 2 * tx)) = res;
}

extern "C" void kernel_launch(void* const* d_in, const int* in_sizes, int n_in,
                              void* d_out, int out_size) {
    // metadata order: strokes [32,8,2] f32 (512 elems), thicknesses [32] f32.
    const float* strokes = (const float*)d_in[0];
    const float* thick   = (const float*)d_in[1];
    if (n_in >= 2 && in_sizes[0] == S && in_sizes[1] == S * PTS * 2) {
        strokes = (const float*)d_in[1];
        thick   = (const float*)d_in[0];
    }
    float* out = (float*)d_out;

    dim3 block(NTHREADS);
    dim3 grid(TPR, TPR);
    render_kernel<<<grid, block>>>(strokes, thick, out);
}